// round 16
// baseline (speedup 1.0000x reference)
#include <cuda_runtime.h>
#include <cuda_bf16.h>
#include <stdint.h>

#define N_NODES  50000
#define EDGE_CNT 1250000
#define PAIR_M   128
#define NUM_PAIRS ((EDGE_CNT + PAIR_M - 1) / PAIR_M)

#define LD_A 168   // bf16 elems; 336B row stride (conflict-free ldmatrix)
#define LD_M 68    // msg fp32 stride: 272B, 16B-aligned rows, 4-bank skew

// fragment-packed weights: slot (kstep, ntile, lane) -> uint2 {b0, b1}
__device__ __align__(16) uint2 g_P1[9 * 16 * 32];
__device__ __align__(16) uint2 g_P2[8 * 16 * 32];
__device__ __align__(16) uint2 g_P3[8 *  8 * 32];
__device__ __align__(16) __nv_bfloat16 g_xbf[N_NODES * 64];
__device__ float g_counts[N_NODES];
__device__ int   g_idx_nonzero;

__device__ __forceinline__ uint32_t pack_bf2(float lo, float hi) {
    uint32_t r;
    asm("cvt.rn.bf16x2.f32 %0, %1, %2;" : "=r"(r) : "f"(hi), "f"(lo));
    return r;
}
__device__ __forceinline__ int load_edge(const void* eidx, int which, int e, bool is64) {
    long long v;
    if (is64) v = ((const long long*)eidx)[(long long)which * EDGE_CNT + e];
    else      v = ((const int*)eidx)[(long long)which * EDGE_CNT + e];
    int n = (int)v;
    return min(max(n, 0), N_NODES - 1);
}
__device__ __forceinline__ void lda_frag(uint32_t* a, const __nv_bfloat16* base, int lane) {
    int mat = lane >> 3, r = lane & 7;
    const __nv_bfloat16* p = base + ((mat & 1) * 8 + r) * LD_A + (mat >> 1) * 8;
    uint32_t addr = (uint32_t)__cvta_generic_to_shared(p);
    asm volatile("ldmatrix.sync.aligned.m8n8.x4.shared.b16 {%0,%1,%2,%3}, [%4];"
                 : "=r"(a[0]), "=r"(a[1]), "=r"(a[2]), "=r"(a[3]) : "r"(addr));
}
__device__ __forceinline__ void mma_bf16(float* c, const uint32_t* a, uint32_t b0, uint32_t b1) {
    asm volatile("mma.sync.aligned.m16n8k16.row.col.f32.bf16.bf16.f32 "
                 "{%0,%1,%2,%3}, {%4,%5,%6,%7}, {%8,%9}, {%0,%1,%2,%3};"
                 : "+f"(c[0]), "+f"(c[1]), "+f"(c[2]), "+f"(c[3])
                 : "r"(a[0]), "r"(a[1]), "r"(a[2]), "r"(a[3]), "r"(b0), "r"(b1));
}

__global__ void zero_kernel(float* __restrict__ out) {
    int i = blockIdx.x * blockDim.x + threadIdx.x;
    int stride = gridDim.x * blockDim.x;
    if (i == 0) g_idx_nonzero = 0;
    for (int j = i; j < N_NODES * 64; j += stride) out[j] = 0.0f;
    for (int j = i; j < N_NODES; j += stride) g_counts[j] = 0.0f;
}
__global__ void detect_kernel(const int* __restrict__ eidx32) {
    int i = blockIdx.x * blockDim.x + threadIdx.x;
    if (eidx32[2 * i + 1] != 0) atomicOr(&g_idx_nonzero, 1);
}
__global__ void xconv_kernel(const float* __restrict__ x) {
    int i = blockIdx.x * blockDim.x + threadIdx.x;
    if (i < N_NODES * 32) {
        float2 v = ((const float2*)x)[i];
        *(uint32_t*)(g_xbf + 2 * i) = pack_bf2(v.x, v.y);
    }
}
__global__ void wpack_kernel(const float* __restrict__ W1, const float* __restrict__ W2,
                             const float* __restrict__ W3) {
    int s = blockIdx.x * blockDim.x + threadIdx.x;
    if (s < 4608) {
        int K = s / 512, rem = s % 512, J = rem >> 5, lane = rem & 31;
        int g = lane >> 2, tc = lane & 3;
        int n = J * 8 + g, k0 = K * 16 + tc * 2;
        g_P1[s] = make_uint2(
            pack_bf2(W1[k0 * 128 + n],       W1[(k0 + 1) * 128 + n]),
            pack_bf2(W1[(k0 + 8) * 128 + n], W1[(k0 + 9) * 128 + n]));
    } else if (s < 4608 + 4096) {
        int j = s - 4608;
        int K = j / 512, rem = j % 512, J = rem >> 5, lane = rem & 31;
        int g = lane >> 2, tc = lane & 3;
        int n = J * 8 + g, k0 = K * 16 + tc * 2;
        g_P2[j] = make_uint2(
            pack_bf2(W2[k0 * 128 + n],       W2[(k0 + 1) * 128 + n]),
            pack_bf2(W2[(k0 + 8) * 128 + n], W2[(k0 + 9) * 128 + n]));
    } else if (s < 4608 + 4096 + 2048) {
        int j = s - 8704;
        int K = j / 256, rem = j % 256, J = rem >> 5, lane = rem & 31;
        int g = lane >> 2, tc = lane & 3;
        int n = J * 8 + g, k0 = K * 16 + tc * 2;
        g_P3[j] = make_uint2(
            pack_bf2(W3[k0 * 64 + n],       W3[(k0 + 1) * 64 + n]),
            pack_bf2(W3[(k0 + 8) * 64 + n], W3[(k0 + 9) * 64 + n]));
    }
}
__global__ void finalize_kernel(const float* __restrict__ x, float* __restrict__ out) {
    int i = blockIdx.x * blockDim.x + threadIdx.x;
    if (i < N_NODES * 64) {
        float c = g_counts[i >> 6];
        out[i] = x[i] + out[i] / fmaxf(c, 1.0f);
    }
}

__global__ void __launch_bounds__(256, 2)
gnn_mma(const void* __restrict__ eidx, const float* __restrict__ ef,
        const float* __restrict__ b1, const float* __restrict__ b2,
        const float* __restrict__ b3, float* __restrict__ out) {
    __shared__ __align__(16) __nv_bfloat16 s_A[2][64 * LD_A];  // A1/h1/h2; GEMM3 msg overlay
    __shared__ float s_b[320];
    __shared__ int   s_tgt[PAIR_M];
    __shared__ int   s_node[256];

    const int tid = threadIdx.x;
    const int w = tid >> 5, lane = tid & 31;
    const int strip = w & 3, colh = w >> 2;
    const int rows16 = strip * 16;
    const int g = lane >> 2, tc = lane & 3;
    const bool is64 = (g_idx_nonzero == 0);
    const int base = blockIdx.x * PAIR_M;
    float* s_msg = (float*)s_A;   // [128][LD_M] fp32 overlay (34816B <= 43008B)

    // ---- phase 1: bias + edge-node resolution ----
    if (tid < 128) { s_b[tid] = b1[tid]; s_b[128 + tid] = b2[tid]; }
    if (tid < 64)  s_b[256 + tid] = b3[tid];
    {
        int m = tid >> 1, half = tid & 1;
        int e = min(base + m, EDGE_CNT - 1);   // clamp; invalid rows never scattered
        int node = load_edge(eidx, half, e, is64);
        s_node[tid] = node;
        if (half) s_tgt[m] = node;
    }
    __syncthreads();

    // ---- phase 2: warp-cooperative x gather (1 row = 1 coalesced 128B line) ----
    {
        const uint32_t* xsrc = (const uint32_t*)g_xbf;
#pragma unroll 4
        for (int i = 0; i < 32; i++) {
            int j = w * 32 + i;               // job: (edge m, half)
            int node = s_node[j];             // LDS broadcast
            uint32_t v = xsrc[node * 32 + lane];
            int m = j >> 1, h = j & 1;
            *(uint32_t*)(s_A[m >> 6] + (m & 63) * LD_A + h * 64 + lane * 2) = v;
        }
    }
    // ---- ef gather: contiguous per tile, fully coalesced ----
#pragma unroll
    for (int it = 0; it < 2; it++) {
        int q = it * 256 + tid;               // float4 slot: 128 edges x 4
        int el = q >> 2, fi = q & 3;
        int e = min(base + el, EDGE_CNT - 1);
        float4 v = ((const float4*)ef)[(long long)e * 4 + fi];
        *(uint2*)(s_A[el >> 6] + (el & 63) * LD_A + 128 + fi * 4) =
            make_uint2(pack_bf2(v.x, v.y), pack_bf2(v.z, v.w));
    }
    __syncthreads();

    // ---- GEMM1 ----
    {
        float c0[8][4] = {}, c1[8][4] = {};
#pragma unroll
        for (int k = 0; k < 9; k++) {
            uint32_t a0[4], a1[4];
            lda_frag(a0, s_A[0] + rows16 * LD_A + k * 16, lane);
            lda_frag(a1, s_A[1] + rows16 * LD_A + k * 16, lane);
#pragma unroll
            for (int j = 0; j < 8; j++) {
                uint2 b = g_P1[(k * 16 + colh * 8 + j) * 32 + lane];
                mma_bf16(c0[j], a0, b.x, b.y);
                mma_bf16(c1[j], a1, b.x, b.y);
            }
        }
        __syncthreads();
#pragma unroll
        for (int j = 0; j < 8; j++) {
            int col = colh * 64 + j * 8 + tc * 2;
            float bb0 = s_b[col], bb1 = s_b[col + 1];
            *(uint32_t*)(s_A[0] + (rows16 + g) * LD_A + col) =
                pack_bf2(fmaxf(c0[j][0] + bb0, 0.f), fmaxf(c0[j][1] + bb1, 0.f));
            *(uint32_t*)(s_A[0] + (rows16 + 8 + g) * LD_A + col) =
                pack_bf2(fmaxf(c0[j][2] + bb0, 0.f), fmaxf(c0[j][3] + bb1, 0.f));
            *(uint32_t*)(s_A[1] + (rows16 + g) * LD_A + col) =
                pack_bf2(fmaxf(c1[j][0] + bb0, 0.f), fmaxf(c1[j][1] + bb1, 0.f));
            *(uint32_t*)(s_A[1] + (rows16 + 8 + g) * LD_A + col) =
                pack_bf2(fmaxf(c1[j][2] + bb0, 0.f), fmaxf(c1[j][3] + bb1, 0.f));
        }
    }
    __syncthreads();

    // ---- GEMM2 (in-place) ----
    {
        float c0[8][4] = {}, c1[8][4] = {};
#pragma unroll
        for (int k = 0; k < 8; k++) {
            uint32_t a0[4], a1[4];
            lda_frag(a0, s_A[0] + rows16 * LD_A + k * 16, lane);
            lda_frag(a1, s_A[1] + rows16 * LD_A + k * 16, lane);
#pragma unroll
            for (int j = 0; j < 8; j++) {
                uint2 b = g_P2[(k * 16 + colh * 8 + j) * 32 + lane];
                mma_bf16(c0[j], a0, b.x, b.y);
                mma_bf16(c1[j], a1, b.x, b.y);
            }
        }
        __syncthreads();
#pragma unroll
        for (int j = 0; j < 8; j++) {
            int col = colh * 64 + j * 8 + tc * 2;
            float bb0 = s_b[128 + col], bb1 = s_b[128 + col + 1];
            *(uint32_t*)(s_A[0] + (rows16 + g) * LD_A + col) =
                pack_bf2(fmaxf(c0[j][0] + bb0, 0.f), fmaxf(c0[j][1] + bb1, 0.f));
            *(uint32_t*)(s_A[0] + (rows16 + 8 + g) * LD_A + col) =
                pack_bf2(fmaxf(c0[j][2] + bb0, 0.f), fmaxf(c0[j][3] + bb1, 0.f));
            *(uint32_t*)(s_A[1] + (rows16 + g) * LD_A + col) =
                pack_bf2(fmaxf(c1[j][0] + bb0, 0.f), fmaxf(c1[j][1] + bb1, 0.f));
            *(uint32_t*)(s_A[1] + (rows16 + 8 + g) * LD_A + col) =
                pack_bf2(fmaxf(c1[j][2] + bb0, 0.f), fmaxf(c1[j][3] + bb1, 0.f));
        }
    }
    __syncthreads();

    // ---- GEMM3: msg = h2 @ W3 + b3 -> smem; then coalesced red.v4 scatter ----
    {
        float c0[4][4] = {}, c1[4][4] = {};
#pragma unroll
        for (int k = 0; k < 8; k++) {
            uint32_t a0[4], a1[4];
            lda_frag(a0, s_A[0] + rows16 * LD_A + k * 16, lane);
            lda_frag(a1, s_A[1] + rows16 * LD_A + k * 16, lane);
#pragma unroll
            for (int j = 0; j < 4; j++) {
                uint2 b = g_P3[(k * 8 + colh * 4 + j) * 32 + lane];
                mma_bf16(c0[j], a0, b.x, b.y);
                mma_bf16(c1[j], a1, b.x, b.y);
            }
        }
        __syncthreads();   // h2 reads complete; s_A region becomes fp32 msg buffer
#pragma unroll
        for (int j = 0; j < 4; j++) {
            int cj = colh * 32 + j * 8 + tc * 2;
            float bb0 = s_b[256 + cj], bb1 = s_b[256 + cj + 1];
            *(float2*)(s_msg + (rows16 + g) * LD_M + cj) =
                make_float2(c0[j][0] + bb0, c0[j][1] + bb1);
            *(float2*)(s_msg + (rows16 + 8 + g) * LD_M + cj) =
                make_float2(c0[j][2] + bb0, c0[j][3] + bb1);
            *(float2*)(s_msg + (64 + rows16 + g) * LD_M + cj) =
                make_float2(c1[j][0] + bb0, c1[j][1] + bb1);
            *(float2*)(s_msg + (64 + rows16 + 8 + g) * LD_M + cj) =
                make_float2(c1[j][2] + bb0, c1[j][3] + bb1);
        }
        __syncthreads();

        // scatter: 2048 slots (128 edges x 16 col-quads), 8 per thread
        for (int s = 0; s < 8; s++) {
            int slot = tid + 256 * s;
            int m = slot >> 4;
            int q = slot & 15;
            if (base + m < EDGE_CNT) {
                int tgt = s_tgt[m];
                float4 v = *(float4*)(s_msg + m * LD_M + q * 4);
                asm volatile("red.global.add.v4.f32 [%0], {%1, %2, %3, %4};"
                             :: "l"(out + (long long)tgt * 64 + q * 4),
                                "f"(v.x), "f"(v.y), "f"(v.z), "f"(v.w) : "memory");
                if (q == 0) atomicAdd(&g_counts[tgt], 1.0f);
            }
        }
    }
}

extern "C" void kernel_launch(void* const* d_in, const int* in_sizes, int n_in,
                              void* d_out, int out_size) {
    const float *x = 0, *ef = 0, *W1 = 0, *W2 = 0, *W3 = 0, *b3 = 0;
    const float *b1 = 0, *b2 = 0;
    const void  *ei = 0;
    for (int i = 0; i < n_in; i++) {
        int s = in_sizes[i];
        if      (s == N_NODES * 64)  x  = (const float*)d_in[i];
        else if (s == 2 * EDGE_CNT)  ei = d_in[i];
        else if (s == EDGE_CNT * 16) ef = (const float*)d_in[i];
        else if (s == 144 * 128)     W1 = (const float*)d_in[i];
        else if (s == 128 * 128)     W2 = (const float*)d_in[i];
        else if (s == 128 * 64)      W3 = (const float*)d_in[i];
        else if (s == 64)            b3 = (const float*)d_in[i];
        else if (s == 128)           { if (!b1) b1 = (const float*)d_in[i]; else b2 = (const float*)d_in[i]; }
    }
    float* out = (float*)d_out;

    zero_kernel<<<2048, 256>>>(out);
    detect_kernel<<<16, 256>>>((const int*)ei);
    xconv_kernel<<<(N_NODES * 32 + 255) / 256, 256>>>(x);
    wpack_kernel<<<(10752 + 255) / 256, 256>>>(W1, W2, W3);
    gnn_mma<<<NUM_PAIRS, 256>>>(ei, ef, b1, b2, b3, out);
    finalize_kernel<<<(N_NODES * 64 + 255) / 256, 256>>>(x, out);
}